// round 1
// baseline (speedup 1.0000x reference)
#include <cuda_runtime.h>
#include <math.h>

#define BB      64
#define TT      100
#define NN      20000
#define NCH     16
#define CHUNK   (NN / NCH)   // 1250
#define THREADS 128

// Scratch (no allocation allowed in kernel_launch)
__device__ float g_pmin[BB * TT * NCH];
__device__ int   g_pidx[BB * TT * NCH];
__device__ float g_persum[BB];

// ---------------------------------------------------------------------------
// Kernel 1: per (b, chunk) — transform chunk into local frame, cache in SMEM,
// each thread (= one waypoint) scans the chunk for the running min of
// q = 0.5*|p|^2 - w.p   (argmin-equivalent to squared distance).
// ---------------------------------------------------------------------------
__global__ void __launch_bounds__(THREADS) nn_kernel(
    const float* __restrict__ poses,     // [B,4,4] row-major
    const float* __restrict__ wpts,      // [B,T,3]
    const float* __restrict__ boundary)  // [4,N]
{
    __shared__ float4 pts[CHUNK];

    const int ch  = blockIdx.x;
    const int b   = blockIdx.y;
    const int tid = threadIdx.x;

    // SE(3) inverse: p_local = R^T (p_global - t)
    const float* P = poses + b * 16;
    const float r00 = P[0], r01 = P[1], r02 = P[2],  tx = P[3];
    const float r10 = P[4], r11 = P[5], r12 = P[6],  ty = P[7];
    const float r20 = P[8], r21 = P[9], r22 = P[10], tz = P[11];

    const int base = ch * CHUNK;
    #pragma unroll 2
    for (int i = tid; i < CHUNK; i += THREADS) {
        float px = boundary[0 * NN + base + i];
        float py = boundary[1 * NN + base + i];
        float pz = boundary[2 * NN + base + i];
        float dx = px - tx, dy = py - ty, dz = pz - tz;
        float lx = fmaf(r00, dx, fmaf(r10, dy, r20 * dz));
        float ly = fmaf(r01, dx, fmaf(r11, dy, r21 * dz));
        float lz = fmaf(r02, dx, fmaf(r12, dy, r22 * dz));
        float c  = 0.5f * fmaf(lx, lx, fmaf(ly, ly, lz * lz));
        pts[i] = make_float4(lx, ly, lz, c);
    }
    __syncthreads();

    const int t = tid;
    if (t >= TT) return;

    const float* w = wpts + (b * TT + t) * 3;
    const float wx = w[0], wy = w[1], wz = w[2];

    // Two independent min chains to break the SEL dependency chain.
    float best0 = INFINITY, best1 = INFINITY;
    int   bi0 = 0,          bi1 = 1;

    #pragma unroll 5
    for (int n = 0; n < CHUNK; n += 2) {
        float4 A = pts[n];
        float4 C = pts[n + 1];
        float q0 = fmaf(-wx, A.x, A.w);
        q0 = fmaf(-wy, A.y, q0);
        q0 = fmaf(-wz, A.z, q0);
        float q1 = fmaf(-wx, C.x, C.w);
        q1 = fmaf(-wy, C.y, q1);
        q1 = fmaf(-wz, C.z, q1);
        if (q0 < best0) { best0 = q0; bi0 = n; }
        if (q1 < best1) { best1 = q1; bi1 = n + 1; }
    }

    float bq; int bn;
    if (best0 <= best1) { bq = best0; bn = bi0; }
    else                { bq = best1; bn = bi1; }

    const int o = (b * TT + t) * NCH + ch;
    g_pmin[o] = bq;
    g_pidx[o] = base + bn;
}

// ---------------------------------------------------------------------------
// Kernel 2: per-b block. For each waypoint, reduce the NCH partials, fetch the
// winning boundary point + normal, transform, dot, ExpRelu, block-sum over T.
// ---------------------------------------------------------------------------
__global__ void __launch_bounds__(128) finish_kernel(
    const float* __restrict__ poses,
    const float* __restrict__ wpts,
    const float* __restrict__ boundary,
    const float* __restrict__ nrms)      // [3,N]
{
    const int b = blockIdx.x;
    const int t = threadIdx.x;

    float val = 0.0f;
    if (t < TT) {
        const float* pm = g_pmin + (b * TT + t) * NCH;
        const int*   pi = g_pidx + (b * TT + t) * NCH;
        float bq = pm[0];
        int   bn = pi[0];
        #pragma unroll
        for (int ch = 1; ch < NCH; ++ch) {
            float q = pm[ch];
            int   i = pi[ch];
            if (q < bq) { bq = q; bn = i; }
        }

        const float* P = poses + b * 16;
        const float r00 = P[0], r01 = P[1], r02 = P[2],  tx = P[3];
        const float r10 = P[4], r11 = P[5], r12 = P[6],  ty = P[7];
        const float r20 = P[8], r21 = P[9], r22 = P[10], tz = P[11];

        // closest point -> local frame
        float px = boundary[0 * NN + bn];
        float py = boundary[1 * NN + bn];
        float pz = boundary[2 * NN + bn];
        float dx = px - tx, dy = py - ty, dz = pz - tz;
        float cpx = fmaf(r00, dx, fmaf(r10, dy, r20 * dz));
        float cpy = fmaf(r01, dx, fmaf(r11, dy, r21 * dz));
        float cpz = fmaf(r02, dx, fmaf(r12, dy, r22 * dz));

        // closest normal -> local frame (rotation only)
        float nx = nrms[0 * NN + bn];
        float ny = nrms[1 * NN + bn];
        float nz = nrms[2 * NN + bn];
        float cnx = fmaf(r00, nx, fmaf(r10, ny, r20 * nz));
        float cny = fmaf(r01, nx, fmaf(r11, ny, r21 * nz));
        float cnz = fmaf(r02, nx, fmaf(r12, ny, r22 * nz));

        const float* w = wpts + (b * TT + t) * 3;
        float d = (w[0] - cpx) * cnx + (w[1] - cpy) * cny + (w[2] - cpz) * cnz;

        // ExpRelu: alpha=1, beta=0.5
        val = (d > 0.0f) ? (d + 1.0f) : expf(0.5f * d);
    }

    __shared__ float sh[128];
    sh[t] = val;
    __syncthreads();
    #pragma unroll
    for (int s = 64; s > 0; s >>= 1) {
        if (t < s) sh[t] += sh[t + s];
        __syncthreads();
    }
    if (t == 0) g_persum[b] = sh[0];
}

// ---------------------------------------------------------------------------
// Kernel 3: one warp sums the 64 per-b sums -> scalar loss. Deterministic.
// ---------------------------------------------------------------------------
__global__ void final_kernel(float* __restrict__ out)
{
    const int i = threadIdx.x;  // 32 threads
    float s = g_persum[i] + g_persum[i + 32];
    #pragma unroll
    for (int o = 16; o > 0; o >>= 1)
        s += __shfl_down_sync(0xFFFFFFFFu, s, o);
    if (i == 0) out[0] = s * (1.0f / (float)(BB * TT));
}

// ---------------------------------------------------------------------------
extern "C" void kernel_launch(void* const* d_in, const int* in_sizes, int n_in,
                              void* d_out, int out_size)
{
    const float* poses    = (const float*)d_in[0];  // [64,4,4]
    const float* wpts     = (const float*)d_in[1];  // [64,100,3]
    const float* boundary = (const float*)d_in[2];  // [4,20000]
    const float* nrms     = (const float*)d_in[3];  // [3,20000]
    float* out = (float*)d_out;

    dim3 grid1(NCH, BB);
    nn_kernel<<<grid1, THREADS>>>(poses, wpts, boundary);
    finish_kernel<<<BB, 128>>>(poses, wpts, boundary, nrms);
    final_kernel<<<1, 32>>>(out);
}

// round 2
// speedup vs baseline: 1.0390x; 1.0390x over previous
#include <cuda_runtime.h>
#include <math.h>
#include <float.h>

#define BB      64
#define TT      100
#define NN      20000
#define NCH     16
#define CHUNK_REAL 1250
#define CHUNK_PAD  1280
#define SUBCH   320          // points per warp
#define SEGSZ   16
#define NSEG    (SUBCH / SEGSZ)   // 20
#define NSUB    (NCH * 4)    // 64 partials per (b,t)
#define THREADS 128

// Scratch (no allocation allowed in kernel_launch)
__device__ float g_pmin[BB * TT * NSUB];
__device__ int   g_pidx[BB * TT * NSUB];
__device__ float g_persum[BB];

// q = 0.5*|p|^2 - w.p  (argmin-equivalent to squared distance); nw = -w
__device__ __forceinline__ float qval(const float4 p, float nwx, float nwy, float nwz) {
    return fmaf(nwx, p.x, fmaf(nwy, p.y, fmaf(nwz, p.z, p.w)));
}

// ---------------------------------------------------------------------------
// Kernel 1: CTA = (chunk, b). Transform chunk into local frame once (SMEM),
// then each warp scans a 320-point sub-chunk for 4 waypoints per lane using
// value-only segment mins (FMNMX), followed by a 16-point rescan for the index.
// ---------------------------------------------------------------------------
__global__ void __launch_bounds__(THREADS) nn_kernel(
    const float* __restrict__ poses,     // [B,4,4] row-major
    const float* __restrict__ wpts,      // [B,T,3]
    const float* __restrict__ boundary)  // [4,N]
{
    __shared__ float4 pts[CHUNK_PAD];

    const int ch  = blockIdx.x;
    const int b   = blockIdx.y;
    const int tid = threadIdx.x;

    // SE(3) inverse: p_local = R^T (p_global - t)
    const float* P = poses + b * 16;
    const float r00 = P[0], r01 = P[1], r02 = P[2],  tx = P[3];
    const float r10 = P[4], r11 = P[5], r12 = P[6],  ty = P[7];
    const float r20 = P[8], r21 = P[9], r22 = P[10], tz = P[11];

    const int gbase = ch * CHUNK_REAL;
    #pragma unroll 2
    for (int i = tid; i < CHUNK_PAD; i += THREADS) {
        float lx = 0.0f, ly = 0.0f, lz = 0.0f, c = 1e30f;  // pad: never wins
        if (i < CHUNK_REAL) {
            float px = boundary[0 * NN + gbase + i];
            float py = boundary[1 * NN + gbase + i];
            float pz = boundary[2 * NN + gbase + i];
            float dx = px - tx, dy = py - ty, dz = pz - tz;
            lx = fmaf(r00, dx, fmaf(r10, dy, r20 * dz));
            ly = fmaf(r01, dx, fmaf(r11, dy, r21 * dz));
            lz = fmaf(r02, dx, fmaf(r12, dy, r22 * dz));
            c  = 0.5f * fmaf(lx, lx, fmaf(ly, ly, lz * lz));
        }
        pts[i] = make_float4(lx, ly, lz, c);
    }
    __syncthreads();

    const int warp = tid >> 5;
    const int lane = tid & 31;
    const float4* sp = pts + warp * SUBCH;

    // 4 waypoint slots per lane: slot = lane + 32*j (slots >= TT duplicate t=TT-1,
    // computed but never stored).
    float nwx[4], nwy[4], nwz[4];
    int   slot[4];
    #pragma unroll
    for (int j = 0; j < 4; ++j) {
        slot[j] = lane + 32 * j;
        int t = (slot[j] < TT) ? slot[j] : (TT - 1);
        const float* w = wpts + (b * TT + t) * 3;
        nwx[j] = -w[0]; nwy[j] = -w[1]; nwz[j] = -w[2];
    }

    float best[4];
    int   sid[4];
    #pragma unroll
    for (int j = 0; j < 4; ++j) { best[j] = FLT_MAX; sid[j] = 0; }

    for (int s = 0; s < NSEG; ++s) {
        const float4* seg = sp + s * SEGSZ;
        float sv[4];
        #pragma unroll
        for (int j = 0; j < 4; ++j) sv[j] = FLT_MAX;

        #pragma unroll
        for (int k = 0; k < SEGSZ; ++k) {
            float4 p = seg[k];                       // broadcast LDS.128
            #pragma unroll
            for (int j = 0; j < 4; ++j)
                sv[j] = fminf(sv[j], qval(p, nwx[j], nwy[j], nwz[j]));
        }
        #pragma unroll
        for (int j = 0; j < 4; ++j) {
            sid[j]  = (sv[j] < best[j]) ? s : sid[j];
            best[j] = fminf(best[j], sv[j]);
        }
    }

    // Rescan winning segment for the exact (first) index; fmaf chain is
    // bitwise-identical to the scan, so equality is exact.
    #pragma unroll
    for (int j = 0; j < 4; ++j) {
        const float4* seg = sp + sid[j] * SEGSZ;
        int loc = -1;
        #pragma unroll
        for (int k = 0; k < SEGSZ; ++k) {
            float qq = qval(seg[k], nwx[j], nwy[j], nwz[j]);
            if (qq == best[j] && loc < 0) loc = k;
        }
        if (loc < 0) loc = 0;  // unreachable safety
        if (slot[j] < TT) {
            int sub = ch * 4 + warp;
            int o   = (b * TT + slot[j]) * NSUB + sub;
            g_pmin[o] = best[j];
            g_pidx[o] = gbase + warp * SUBCH + sid[j] * SEGSZ + loc;
        }
    }
}

// ---------------------------------------------------------------------------
// Kernel 2: per-b block. Reduce the NSUB partials per waypoint (strict < keeps
// first/lowest global index), fetch winning point + normal, transform, dot,
// ExpRelu, block-sum over T.
// ---------------------------------------------------------------------------
__global__ void __launch_bounds__(128) finish_kernel(
    const float* __restrict__ poses,
    const float* __restrict__ wpts,
    const float* __restrict__ boundary,
    const float* __restrict__ nrms)      // [3,N]
{
    const int b = blockIdx.x;
    const int t = threadIdx.x;

    float val = 0.0f;
    if (t < TT) {
        const float* pm = g_pmin + (b * TT + t) * NSUB;
        const int*   pi = g_pidx + (b * TT + t) * NSUB;
        float bq = pm[0];
        int   bn = pi[0];
        #pragma unroll 8
        for (int s = 1; s < NSUB; ++s) {
            float q = pm[s];
            int   i = pi[s];
            if (q < bq) { bq = q; bn = i; }
        }

        const float* P = poses + b * 16;
        const float r00 = P[0], r01 = P[1], r02 = P[2],  tx = P[3];
        const float r10 = P[4], r11 = P[5], r12 = P[6],  ty = P[7];
        const float r20 = P[8], r21 = P[9], r22 = P[10], tz = P[11];

        // closest point -> local frame
        float px = boundary[0 * NN + bn];
        float py = boundary[1 * NN + bn];
        float pz = boundary[2 * NN + bn];
        float dx = px - tx, dy = py - ty, dz = pz - tz;
        float cpx = fmaf(r00, dx, fmaf(r10, dy, r20 * dz));
        float cpy = fmaf(r01, dx, fmaf(r11, dy, r21 * dz));
        float cpz = fmaf(r02, dx, fmaf(r12, dy, r22 * dz));

        // closest normal -> local frame (rotation only)
        float nx = nrms[0 * NN + bn];
        float ny = nrms[1 * NN + bn];
        float nz = nrms[2 * NN + bn];
        float cnx = fmaf(r00, nx, fmaf(r10, ny, r20 * nz));
        float cny = fmaf(r01, nx, fmaf(r11, ny, r21 * nz));
        float cnz = fmaf(r02, nx, fmaf(r12, ny, r22 * nz));

        const float* w = wpts + (b * TT + t) * 3;
        float d = (w[0] - cpx) * cnx + (w[1] - cpy) * cny + (w[2] - cpz) * cnz;

        // ExpRelu: alpha=1, beta=0.5
        val = (d > 0.0f) ? (d + 1.0f) : expf(0.5f * d);
    }

    __shared__ float sh[128];
    sh[t] = val;
    __syncthreads();
    #pragma unroll
    for (int s = 64; s > 0; s >>= 1) {
        if (t < s) sh[t] += sh[t + s];
        __syncthreads();
    }
    if (t == 0) g_persum[b] = sh[0];
}

// ---------------------------------------------------------------------------
// Kernel 3: one warp sums the 64 per-b sums -> scalar loss. Deterministic.
// ---------------------------------------------------------------------------
__global__ void final_kernel(float* __restrict__ out)
{
    const int i = threadIdx.x;  // 32 threads
    float s = g_persum[i] + g_persum[i + 32];
    #pragma unroll
    for (int o = 16; o > 0; o >>= 1)
        s += __shfl_down_sync(0xFFFFFFFFu, s, o);
    if (i == 0) out[0] = s * (1.0f / (float)(BB * TT));
}

// ---------------------------------------------------------------------------
extern "C" void kernel_launch(void* const* d_in, const int* in_sizes, int n_in,
                              void* d_out, int out_size)
{
    const float* poses    = (const float*)d_in[0];  // [64,4,4]
    const float* wpts     = (const float*)d_in[1];  // [64,100,3]
    const float* boundary = (const float*)d_in[2];  // [4,20000]
    const float* nrms     = (const float*)d_in[3];  // [3,20000]
    float* out = (float*)d_out;

    dim3 grid1(NCH, BB);
    nn_kernel<<<grid1, THREADS>>>(poses, wpts, boundary);
    finish_kernel<<<BB, 128>>>(poses, wpts, boundary, nrms);
    final_kernel<<<1, 32>>>(out);
}